// round 2
// baseline (speedup 1.0000x reference)
#include <cuda_runtime.h>
#include <math.h>

#define NMAX 20000
#define EMAX 320000
#define HDIM 256
#define GNUM 64

typedef unsigned long long ull;

// ---------------- scratch (device globals, no allocation) ----------------
__device__ int   g_cnt_out[NMAX];
__device__ int   g_cnt_in[NMAX];
__device__ int   g_row_off[NMAX + 1];
__device__ int   g_cursor[NMAX];
__device__ int   g_csr_src[EMAX];
__device__ float g_hn[NMAX * HDIM];    // (h * D_out^-1/2) @ W_conv
__device__ float g_hr[NMAX * HDIM];    // relu'd conv output
__device__ float g_gate[NMAX];
__device__ int   g_counts[GNUM];
__device__ int   g_starts[GNUM + 1];

// ---------------- packed f32x2 helpers ----------------
__device__ __forceinline__ ull pk2(float lo, float hi) {
    ull r; asm("mov.b64 %0, {%1,%2};" : "=l"(r) : "f"(lo), "f"(hi)); return r;
}
__device__ __forceinline__ ull fma2(ull a, ull b, ull c) {
    ull d; asm("fma.rn.f32x2 %0, %1, %2, %3;" : "=l"(d) : "l"(a), "l"(b), "l"(c)); return d;
}

// ---------------- init: zero counters only ----------------
__global__ void k_init(int Nn) {
    int i = blockIdx.x * blockDim.x + threadIdx.x;
    if (i < Nn) { g_cnt_out[i] = 0; g_cnt_in[i] = 0; }
    if (i < GNUM) g_counts[i] = 0;
}

// ---------------- degrees + graph counts in one pass ----------------
__global__ void k_build(const int* __restrict__ src, const int* __restrict__ dst,
                        const int* __restrict__ gid, int E, int Nn) {
    int i = blockIdx.x * blockDim.x + threadIdx.x;
    if (i < E) {
        atomicAdd(&g_cnt_out[src[i]], 1);
        atomicAdd(&g_cnt_in[dst[i]], 1);
    }
    if (i < Nn) atomicAdd(&g_counts[gid[i]], 1);
}

// ---------------- single-block scan: CSR row offsets + graph starts ----------------
__global__ void k_scan_all(int Nn) {
    __shared__ int part[1024];
    int t = threadIdx.x;
    int chunk = (Nn + 1023) / 1024;
    int beg = t * chunk;
    int end = min(Nn, beg + chunk);
    int s = 0;
    for (int i = beg; i < end; i++) s += g_cnt_in[i];
    part[t] = s;
    __syncthreads();
    // Hillis-Steele inclusive scan
    for (int off = 1; off < 1024; off <<= 1) {
        int v = (t >= off) ? part[t - off] : 0;
        __syncthreads();
        part[t] += v;
        __syncthreads();
    }
    int run = (t > 0) ? part[t - 1] : 0;
    for (int i = beg; i < end; i++) {
        g_row_off[i] = run;
        g_cursor[i] = run;
        run += g_cnt_in[i];
    }
    if (t == 0) {
        g_row_off[Nn] = part[1023];
        int acc = 0;
        for (int g = 0; g < GNUM; g++) { g_starts[g] = acc; acc += g_counts[g]; }
        g_starts[GNUM] = acc;
    }
}

// ---------------- fill CSR buckets ----------------
__global__ void k_fill(const int* __restrict__ src, const int* __restrict__ dst, int E) {
    int e = blockIdx.x * blockDim.x + threadIdx.x;
    if (e < E) {
        int pos = atomicAdd(&g_cursor[dst[e]], 1);
        g_csr_src[pos] = src[e];
    }
}

// ---------------- GEMM: hn = (h * rsqrt(max(deg_out,1))) @ W_conv ----------------
// 128x64 tile, BK=16, 256 threads, 4(m)x8(n) micro-tile using packed f32x2 FMA
__global__ void k_gemm_hn(const float* __restrict__ h, const float* __restrict__ W,
                          int M) {
    __shared__ float As[16][128];
    __shared__ float Bs[16][64];
    int tid = threadIdx.x;
    int m0 = blockIdx.y * 128;
    int n0 = blockIdx.x * 64;

    // A load mapping: row = tid/2 (0..127), col0 = (tid&1)*8
    int a_r = tid >> 1;
    int a_c0 = (tid & 1) * 8;
    int gm = m0 + a_r;
    float scale = 0.0f;
    if (gm < M) scale = rsqrtf(fmaxf((float)g_cnt_out[gm], 1.0f));

    // B load mapping: row = tid/16 (0..15), col = (tid&15)*4
    int b_r = tid >> 4;
    int b_c = (tid & 15) * 4;

    // compute mapping
    int ty = tid >> 3;   // 0..31 -> m sub-tile of 4
    int tx = tid & 7;    // 0..7  -> n sub-tile of 8

    ull acc[4][4];
#pragma unroll
    for (int i = 0; i < 4; i++)
#pragma unroll
        for (int p = 0; p < 4; p++) acc[i][p] = 0ULL;

    for (int k0 = 0; k0 < HDIM; k0 += 16) {
        float4 av0 = make_float4(0.f, 0.f, 0.f, 0.f);
        float4 av1 = make_float4(0.f, 0.f, 0.f, 0.f);
        if (gm < M) {
            const float* hp = h + (size_t)gm * HDIM + k0 + a_c0;
            av0 = *reinterpret_cast<const float4*>(hp);
            av1 = *reinterpret_cast<const float4*>(hp + 4);
        }
        As[a_c0 + 0][a_r] = av0.x * scale;
        As[a_c0 + 1][a_r] = av0.y * scale;
        As[a_c0 + 2][a_r] = av0.z * scale;
        As[a_c0 + 3][a_r] = av0.w * scale;
        As[a_c0 + 4][a_r] = av1.x * scale;
        As[a_c0 + 5][a_r] = av1.y * scale;
        As[a_c0 + 6][a_r] = av1.z * scale;
        As[a_c0 + 7][a_r] = av1.w * scale;

        *reinterpret_cast<float4*>(&Bs[b_r][b_c]) =
            *reinterpret_cast<const float4*>(W + (size_t)(k0 + b_r) * HDIM + n0 + b_c);
        __syncthreads();

#pragma unroll
        for (int kk = 0; kk < 16; kk++) {
            float4 a4 = *reinterpret_cast<const float4*>(&As[kk][ty * 4]);
            float4 b0 = *reinterpret_cast<const float4*>(&Bs[kk][tx * 8]);
            float4 b1 = *reinterpret_cast<const float4*>(&Bs[kk][tx * 8 + 4]);
            ull aa[4] = {pk2(a4.x, a4.x), pk2(a4.y, a4.y), pk2(a4.z, a4.z), pk2(a4.w, a4.w)};
            ull bb[4] = {pk2(b0.x, b0.y), pk2(b0.z, b0.w), pk2(b1.x, b1.y), pk2(b1.z, b1.w)};
#pragma unroll
            for (int i = 0; i < 4; i++)
#pragma unroll
                for (int p = 0; p < 4; p++)
                    acc[i][p] = fma2(aa[i], bb[p], acc[i][p]);
        }
        __syncthreads();
    }

#pragma unroll
    for (int i = 0; i < 4; i++) {
        int m = m0 + ty * 4 + i;
        if (m < M) {
            ull* op = reinterpret_cast<ull*>(g_hn + (size_t)m * HDIM + n0 + tx * 8);
#pragma unroll
            for (int p = 0; p < 4; p++) op[p] = acc[i][p];
        }
    }
}

// ---------------- aggregation (CSR gather) + scale + bias + relu + gate ----------------
__global__ void k_agg(const float* __restrict__ b_conv,
                      const float* __restrict__ w_gate,
                      const float* __restrict__ b_gate) {
    int n = blockIdx.x;
    int f = threadIdx.x;
    __shared__ float red[256];
    int s = g_row_off[n], e = g_row_off[n + 1];

    float a0 = 0.f, a1 = 0.f, a2 = 0.f, a3 = 0.f;
    int j = s;
    for (; j + 4 <= e; j += 4) {
        int s0 = g_csr_src[j + 0];
        int s1 = g_csr_src[j + 1];
        int s2 = g_csr_src[j + 2];
        int s3 = g_csr_src[j + 3];
        a0 += __ldg(g_hn + (size_t)s0 * HDIM + f);
        a1 += __ldg(g_hn + (size_t)s1 * HDIM + f);
        a2 += __ldg(g_hn + (size_t)s2 * HDIM + f);
        a3 += __ldg(g_hn + (size_t)s3 * HDIM + f);
    }
    for (; j < e; j++)
        a0 += __ldg(g_hn + (size_t)g_csr_src[j] * HDIM + f);
    float acc = (a0 + a1) + (a2 + a3);

    float sc = rsqrtf(fmaxf((float)g_cnt_in[n], 1.0f));
    float v = fmaxf(acc * sc + b_conv[f], 0.0f);
    g_hr[(size_t)n * HDIM + f] = v;

    red[f] = v * w_gate[f];
    __syncthreads();
#pragma unroll
    for (int st = 128; st > 0; st >>= 1) {
        if (f < st) red[f] += red[f + st];
        __syncthreads();
    }
    if (f == 0) g_gate[n] = red[0] + b_gate[0];
}

// ---------------- per-graph pooling: segment softmax + weighted sum ----------------
__global__ void k_pool(float* __restrict__ att_out, float* __restrict__ hg_out) {
    int g = blockIdx.x;
    int s = g_starts[g], e = g_starts[g + 1];
    int tid = threadIdx.x;
    __shared__ float red[256];

    if (s >= e) {
        hg_out[(size_t)g * HDIM + tid] = 0.0f;
        return;
    }
    // max
    float m = -INFINITY;
    for (int n = s + tid; n < e; n += 256) m = fmaxf(m, g_gate[n]);
    red[tid] = m; __syncthreads();
#pragma unroll
    for (int st = 128; st > 0; st >>= 1) {
        if (tid < st) red[tid] = fmaxf(red[tid], red[tid + st]);
        __syncthreads();
    }
    float gm = red[0];
    __syncthreads();
    // exp + sum, stash unnormalized e in att_out
    float sm = 0.0f;
    for (int n = s + tid; n < e; n += 256) {
        float ev = __expf(g_gate[n] - gm);
        att_out[n] = ev;
        sm += ev;
    }
    red[tid] = sm; __syncthreads();
#pragma unroll
    for (int st = 128; st > 0; st >>= 1) {
        if (tid < st) red[tid] += red[tid + st];
        __syncthreads();
    }
    float inv = 1.0f / red[0];
    __syncthreads();
    // weighted sum over nodes, feature = tid, 4-way unroll for MLP
    float c0 = 0.f, c1 = 0.f, c2 = 0.f, c3 = 0.f;
    int n = s;
    for (; n + 4 <= e; n += 4) {
        c0 += att_out[n + 0] * g_hr[(size_t)(n + 0) * HDIM + tid];
        c1 += att_out[n + 1] * g_hr[(size_t)(n + 1) * HDIM + tid];
        c2 += att_out[n + 2] * g_hr[(size_t)(n + 2) * HDIM + tid];
        c3 += att_out[n + 3] * g_hr[(size_t)(n + 3) * HDIM + tid];
    }
    for (; n < e; n++)
        c0 += att_out[n] * g_hr[(size_t)n * HDIM + tid];
    hg_out[(size_t)g * HDIM + tid] = ((c0 + c1) + (c2 + c3)) * inv;
    __syncthreads();
    // normalize att in place
    for (int k = s + tid; k < e; k += 256) att_out[k] *= inv;
}

// ---------------- classifier heads ----------------
__global__ void k_heads(const float* __restrict__ hg,
                        const float* __restrict__ W1, const float* __restrict__ b1,
                        const float* __restrict__ W2, const float* __restrict__ b2,
                        float* __restrict__ probs) {
    int g = blockIdx.x;
    int j = threadIdx.x;
    __shared__ float s_hg[256];
    __shared__ float r0[256], r1[256];
    s_hg[j] = hg[(size_t)g * HDIM + j];
    __syncthreads();
    float acc = b1[j];
#pragma unroll 8
    for (int k = 0; k < HDIM; k++) acc += s_hg[k] * W1[(size_t)k * HDIM + j];
    r0[j] = acc * W2[j * 2 + 0];
    r1[j] = acc * W2[j * 2 + 1];
    __syncthreads();
#pragma unroll
    for (int st = 128; st > 0; st >>= 1) {
        if (j < st) { r0[j] += r0[j + st]; r1[j] += r1[j + st]; }
        __syncthreads();
    }
    if (j == 0) {
        probs[g * 2 + 0] = 1.0f / (1.0f + expf(-(r0[0] + b2[0])));
        probs[g * 2 + 1] = 1.0f / (1.0f + expf(-(r1[0] + b2[1])));
    }
}

// ---------------- launch ----------------
extern "C" void kernel_launch(void* const* d_in, const int* in_sizes, int n_in,
                              void* d_out, int out_size) {
    const float* h      = (const float*)d_in[0];
    const int*   src    = (const int*)d_in[1];
    const int*   dst    = (const int*)d_in[2];
    const int*   gid    = (const int*)d_in[3];
    const float* W_conv = (const float*)d_in[4];
    const float* b_conv = (const float*)d_in[5];
    const float* w_gate = (const float*)d_in[6];
    const float* b_gate = (const float*)d_in[7];
    const float* W1     = (const float*)d_in[8];
    const float* b1     = (const float*)d_in[9];
    const float* W2     = (const float*)d_in[10];
    const float* b2     = (const float*)d_in[11];

    int Nn = in_sizes[3];
    int E  = in_sizes[1];

    float* out   = (float*)d_out;
    float* probs = out;                       // [G*2]
    float* att   = out + GNUM * 2;            // [N]
    float* hg    = out + GNUM * 2 + Nn;       // [G*H]

    int NE = E > Nn ? E : Nn;
    k_init<<<(Nn + 255) / 256, 256>>>(Nn);
    k_build<<<(NE + 255) / 256, 256>>>(src, dst, gid, E, Nn);
    k_scan_all<<<1, 1024>>>(Nn);
    k_fill<<<(E + 255) / 256, 256>>>(src, dst, E);
    dim3 gg(HDIM / 64, (Nn + 127) / 128);
    k_gemm_hn<<<gg, 256>>>(h, W_conv, Nn);
    k_agg<<<Nn, 256>>>(b_conv, w_gate, b_gate);
    k_pool<<<GNUM, 256>>>(att, hg);
    k_heads<<<GNUM, 256>>>(hg, W1, b1, W2, b2, probs);
}